// round 13
// baseline (speedup 1.0000x reference)
#include <cuda_runtime.h>
#include <cuda_fp16.h>
#include <math.h>
#include <stdint.h>

#define BATCH   64
#define NTOK    1024
#define DIM     512
#define HEADS   8
#define HD      24
#define HHDIM   192
#define HID     2048
#define NROWS   (BATCH*NTOK)   // 65536

typedef __half fp16;

// ---------------- scratch (device globals) ----------------
__device__ fp16  g_xn_hi [(size_t)NROWS * DIM];
__device__ fp16  g_xn_lo [(size_t)NROWS * DIM];     // only used by f/v (LN1)
__device__ float g_feat  [(size_t)NROWS * HHDIM];
__device__ float g_val   [(size_t)NROWS * HHDIM];
__device__ fp16  g_at_hi [(size_t)NROWS * HHDIM];
__device__ float g_x1    [(size_t)NROWS * DIM];
__device__ fp16  g_hid_hi[(size_t)NROWS * HID];
// weights: f+v concatenated (384 rows) hi/lo; proj/fc1/fc2 hi-only
__device__ fp16  g_fvw_hi[2*HHDIM*DIM], g_fvw_lo[2*HHDIM*DIM];
__device__ fp16  g_pw_hi[DIM*HHDIM];
__device__ fp16  g_w1_hi[HID*DIM];
__device__ fp16  g_w2_hi[DIM*HID];

// ---------------- helpers ----------------
__device__ __forceinline__ uint32_t smem_u32(const void* p) {
    uint32_t a;
    asm("{ .reg .u64 t; cvta.to.shared.u64 t, %1; cvt.u32.u64 %0, t; }" : "=r"(a) : "l"(p));
    return a;
}
__device__ __forceinline__ void cp16(uint32_t saddr, const void* g) {
    asm volatile("cp.async.cg.shared.global [%0], [%1], 16;" :: "r"(saddr), "l"(g));
}
#define CP_COMMIT() asm volatile("cp.async.commit_group;" ::: "memory")
template<int N>
__device__ __forceinline__ void cp_wait() {
    asm volatile("cp.async.wait_group %0;" :: "n"(N) : "memory");
}
__device__ __forceinline__ void ldm_x4(uint32_t* r, uint32_t addr) {
    asm volatile("ldmatrix.sync.aligned.m8n8.x4.shared.b16 {%0,%1,%2,%3}, [%4];"
        : "=r"(r[0]), "=r"(r[1]), "=r"(r[2]), "=r"(r[3]) : "r"(addr));
}
__device__ __forceinline__ void mma_f16(float* c, const uint32_t* a, const uint32_t* b) {
    asm volatile(
        "mma.sync.aligned.m16n8k16.row.col.f32.f16.f16.f32 "
        "{%0,%1,%2,%3}, {%4,%5,%6,%7}, {%8,%9}, {%0,%1,%2,%3};"
        : "+f"(c[0]), "+f"(c[1]), "+f"(c[2]), "+f"(c[3])
        : "r"(a[0]), "r"(a[1]), "r"(a[2]), "r"(a[3]), "r"(b[0]), "r"(b[1]));
}

// ---------------- fp32 -> fp16 hi/lo conversions ----------------
__global__ void cvt_kernel(const float* __restrict__ s, fp16* __restrict__ hi,
                           fp16* __restrict__ lo, int n) {
    int i = blockIdx.x * blockDim.x + threadIdx.x;
    if (i < n) {
        float v = s[i];
        fp16 h = __float2half_rn(v);
        hi[i] = h;
        lo[i] = __float2half_rn(v - __half2float(h));
    }
}
__global__ void cvt_hi_kernel(const float* __restrict__ s, fp16* __restrict__ hi, int n) {
    int i = blockIdx.x * blockDim.x + threadIdx.x;
    if (i < n) hi[i] = __float2half_rn(s[i]);
}

// ---------------- LayerNorm -> fp16 hi (+ optional lo) ----------------
template<int WRITE_LO>
__global__ void ln_kernel(const float* __restrict__ x, const float* __restrict__ g,
                          const float* __restrict__ b, fp16* __restrict__ yh,
                          fp16* __restrict__ yl) {
    int row = blockIdx.x;
    const float4* xr = (const float4*)(x + (size_t)row * DIM);
    float4 v = xr[threadIdx.x];
    float s  = v.x + v.y + v.z + v.w;
    float sq = v.x*v.x + v.y*v.y + v.z*v.z + v.w*v.w;
    #pragma unroll
    for (int o = 16; o; o >>= 1) {
        s  += __shfl_down_sync(0xffffffffu, s,  o);
        sq += __shfl_down_sync(0xffffffffu, sq, o);
    }
    __shared__ float rs[4], rq[4];
    __shared__ float s_mean, s_rstd;
    int lane = threadIdx.x & 31, w = threadIdx.x >> 5;
    if (lane == 0) { rs[w] = s; rq[w] = sq; }
    __syncthreads();
    if (threadIdx.x == 0) {
        float S = rs[0]+rs[1]+rs[2]+rs[3];
        float Q = rq[0]+rq[1]+rq[2]+rq[3];
        float m = S * (1.0f/DIM);
        float var = Q * (1.0f/DIM) - m*m;
        s_mean = m; s_rstd = rsqrtf(var + 1e-5f);
    }
    __syncthreads();
    float m = s_mean, r = s_rstd;
    float4 gg = ((const float4*)g)[threadIdx.x];
    float4 bb = ((const float4*)b)[threadIdx.x];
    float o0 = (v.x-m)*r*gg.x + bb.x, o1 = (v.y-m)*r*gg.y + bb.y;
    float o2 = (v.z-m)*r*gg.z + bb.z, o3 = (v.w-m)*r*gg.w + bb.w;
    fp16 h0 = __float2half_rn(o0), h1 = __float2half_rn(o1);
    fp16 h2 = __float2half_rn(o2), h3 = __float2half_rn(o3);
    __half2* hp = (__half2*)(yh + (size_t)row*DIM);
    hp[2*threadIdx.x]   = __halves2half2(h0, h1);
    hp[2*threadIdx.x+1] = __halves2half2(h2, h3);
    if (WRITE_LO) {
        __half2* lp = (__half2*)(yl + (size_t)row*DIM);
        lp[2*threadIdx.x]   = __halves2half2(__float2half_rn(o0-__half2float(h0)),
                                             __float2half_rn(o1-__half2float(h1)));
        lp[2*threadIdx.x+1] = __halves2half2(__float2half_rn(o2-__half2float(h2)),
                                             __float2half_rn(o3-__half2float(h3)));
    }
}

// ---------------- HMMA GEMM: C = A @ B^T, fp16 (optionally hi/lo emulated) ----
// 128 threads, 4 warps in 2x2: warp tile 64 x (BN/2).
// ALO: include Al*Bh term.  BLO: include Ah*Bl term.
// EPI 0: C=acc+bias (fp32)        EPI 1: C=acc+bias+Res (fp32)
// EPI 2: gelu(acc+bias) -> fp16   EPI 3: split output (cols<192 -> Cf/bias, else Cf2/bias2)
#define ROWB 80   // 64B data + 16B pad: conflict-free ldmatrix

template<int BN, int EPI, int ALO, int BLO>
__global__ __launch_bounds__(128, 2)
void gemm_mma(const fp16* __restrict__ Ahi, const fp16* __restrict__ Alo,
              const fp16* __restrict__ Bhi, const fp16* __restrict__ Blo,
              const float* __restrict__ bias, const float* __restrict__ bias2,
              const float* __restrict__ Res,
              float* __restrict__ Cf, float* __restrict__ Cf2, fp16* __restrict__ Chi,
              int N, int K) {
    constexpr int NT = BN / 16;              // n8-tiles per warp (warp covers BN/2)
    constexpr int A_BYTES = 128 * ROWB;
    constexpr int B_BYTES = BN * ROWB;
    constexpr int SS = (1+ALO)*A_BYTES + (1+BLO)*B_BYTES;

    extern __shared__ char smem[];
    const uint32_t sbase = smem_u32(smem);
    const int tid  = threadIdx.x;
    const int wid  = tid >> 5;
    const int lane = tid & 31;
    const int warp_m = wid & 1;              // 2 m-groups of 64 rows
    const int warp_n = wid >> 1;             // 2 n-groups of BN/2 cols
    const int bm = blockIdx.y * 128;
    const int bn = blockIdx.x * BN;

    // ldmatrix lane geometry
    const int lr = lane & 7;
    const int g8 = lane >> 3;
    const int a_row0 = warp_m*64 + (g8 & 1)*8 + lr;       // + sub*16, sub=0..3
    const int a_ch   = (g8 >> 1);                          // +cb
    const int b_row0 = warp_n*(NT*8) + (g8 >> 1)*8 + lr;   // + t2*16
    const int b_ch   = (g8 & 1);                           // +cb

    float acc[4][NT][4];
    #pragma unroll
    for (int s = 0; s < 4; ++s)
        #pragma unroll
        for (int t = 0; t < NT; ++t)
            #pragma unroll
            for (int j = 0; j < 4; ++j) acc[s][t][j] = 0.0f;

    auto load_stage = [&](int st, int k0) {
        uint32_t sA_hi = sbase + st*SS;
        uint32_t sA_lo = sA_hi + A_BYTES;                   // valid iff ALO
        uint32_t sB_hi = sA_hi + (1+ALO)*A_BYTES;
        uint32_t sB_lo = sB_hi + B_BYTES;                   // valid iff BLO
        #pragma unroll
        for (int it = 0; it < 4; ++it) {            // A: 128 rows x 4 chunks
            int idx = tid + it*128;
            int r = idx >> 2, c = idx & 3;
            size_t go = (size_t)(bm + r)*K + k0 + c*8;
            uint32_t so = (uint32_t)(r*ROWB + c*16);
            cp16(sA_hi + so, Ahi + go);
            if (ALO) cp16(sA_lo + so, Alo + go);
        }
        #pragma unroll
        for (int it = 0; it < BN/32; ++it) {        // B: BN rows x 4 chunks
            int idx = tid + it*128;
            int r = idx >> 2, c = idx & 3;
            size_t go = (size_t)(bn + r)*K + k0 + c*8;
            uint32_t so = (uint32_t)(r*ROWB + c*16);
            cp16(sB_hi + so, Bhi + go);
            if (BLO) cp16(sB_lo + so, Blo + go);
        }
    };

    const int nk = K / 32;
    load_stage(0, 0);  CP_COMMIT();
    load_stage(1, 32); CP_COMMIT();

    for (int c = 0; c < nk; ++c) {
        cp_wait<1>();
        __syncthreads();
        int st = c % 3;
        uint32_t sA_hi = sbase + st*SS;
        uint32_t sA_lo = sA_hi + A_BYTES;
        uint32_t sB_hi = sA_hi + (1+ALO)*A_BYTES;
        uint32_t sB_lo = sB_hi + B_BYTES;

        uint32_t ah[4][4], al[4][4], bb[NT][2];
        #pragma unroll
        for (int k16 = 0; k16 < 2; ++k16) {
            int cb = k16*2;
            #pragma unroll
            for (int sub = 0; sub < 4; ++sub) {
                uint32_t ao = (uint32_t)((a_row0 + sub*16)*ROWB + (cb + a_ch)*16);
                ldm_x4(ah[sub], sA_hi + ao);
                if (ALO) ldm_x4(al[sub], sA_lo + ao);
            }
            #pragma unroll
            for (int t2 = 0; t2 < NT/2; ++t2) {
                uint32_t bo = (uint32_t)((b_row0 + t2*16)*ROWB + (cb + b_ch)*16);
                ldm_x4(&bb[2*t2][0], sB_hi + bo);
            }
            #pragma unroll
            for (int sub = 0; sub < 4; ++sub)
                #pragma unroll
                for (int t = 0; t < NT; ++t) {
                    mma_f16(acc[sub][t], ah[sub], bb[t]);            // hi*hi
                    if (ALO) mma_f16(acc[sub][t], al[sub], bb[t]);   // lo*hi
                }
            if (BLO) {
                #pragma unroll
                for (int t2 = 0; t2 < NT/2; ++t2) {
                    uint32_t bo = (uint32_t)((b_row0 + t2*16)*ROWB + (cb + b_ch)*16);
                    ldm_x4(&bb[2*t2][0], sB_lo + bo);
                }
                #pragma unroll
                for (int sub = 0; sub < 4; ++sub)
                    #pragma unroll
                    for (int t = 0; t < NT; ++t)
                        mma_f16(acc[sub][t], ah[sub], bb[t]);        // hi*lo
            }
        }
        __syncthreads();
        if (c + 2 < nk) load_stage((c + 2) % 3, (c + 2)*32);
        CP_COMMIT();
    }

    // ---------------- epilogue ----------------
    const int mbase = bm + warp_m*64;
    const int nb0   = bn + warp_n*(NT*8);
    #pragma unroll
    for (int sub = 0; sub < 4; ++sub) {
        int r0 = mbase + sub*16 + (lane >> 2);
        #pragma unroll
        for (int t = 0; t < NT; ++t) {
            int c0 = nb0 + t*8 + (lane & 3)*2;
            float b0, b1;
            float* dst = Cf;
            int cc = c0;
            if (EPI == 3) {
                if (c0 >= HHDIM) { dst = Cf2; cc = c0 - HHDIM; b0 = bias2[cc]; b1 = bias2[cc+1]; }
                else             { b0 = bias[c0]; b1 = bias[c0+1]; }
            } else {
                b0 = bias[c0]; b1 = bias[c0+1];
            }
            float v00 = acc[sub][t][0] + b0, v01 = acc[sub][t][1] + b1;
            float v10 = acc[sub][t][2] + b0, v11 = acc[sub][t][3] + b1;
            size_t gi0 = (size_t)r0*N + cc;
            size_t gi1 = (size_t)(r0+8)*N + cc;
            if (EPI == 0 || EPI == 3) {
                *(float2*)(dst + gi0) = make_float2(v00, v01);
                *(float2*)(dst + gi1) = make_float2(v10, v11);
            } else if (EPI == 1) {
                float2 r0v = *(const float2*)(Res + gi0);
                float2 r1v = *(const float2*)(Res + gi1);
                *(float2*)(Cf + gi0) = make_float2(v00 + r0v.x, v01 + r0v.y);
                *(float2*)(Cf + gi1) = make_float2(v10 + r1v.x, v11 + r1v.y);
            } else {
                float g00 = 0.5f*v00*(1.0f + erff(v00*0.7071067811865475f));
                float g01 = 0.5f*v01*(1.0f + erff(v01*0.7071067811865475f));
                float g10 = 0.5f*v10*(1.0f + erff(v10*0.7071067811865475f));
                float g11 = 0.5f*v11*(1.0f + erff(v11*0.7071067811865475f));
                *(__half2*)(Chi + gi0) = __halves2half2(
                    __float2half_rn(g00), __float2half_rn(g01));
                *(__half2*)(Chi + gi1) = __halves2half2(
                    __float2half_rn(g10), __float2half_rn(g11));
            }
        }
    }
}

// ---------------- Cluster3D core: one block per (batch, head) ----------------
#define CL_SMEM ((1024*24*2 + 16*24*3 + 16 + 1024) * 4 + 1024 * 4)
#define CL_THREADS 512

__global__ __launch_bounds__(CL_THREADS, 1)
void cluster_kernel(const float* __restrict__ feat, const float* __restrict__ val,
                    const float* __restrict__ alpha_p, const float* __restrict__ beta_p,
                    fp16* __restrict__ out_hi) {
    extern __shared__ float sm[];
    float* fh   = sm;
    float* vh   = fh + 1024*24;
    float* cn   = vh + 1024*24;
    float* vcen = cn + 16*24;
    float* num  = vcen + 16*24;
    float* cnt  = num + 16*24;
    float* sval = cnt + 16;
    int*   sidx = (int*)(sval + 1024);

    const int bh = blockIdx.x;
    const int b  = bh >> 3;
    const int h  = bh & 7;
    const int tid = threadIdx.x;
    const float alpha = *alpha_p, beta = *beta_p;
    const size_t base = (size_t)b * NTOK * HHDIM + (size_t)h * HD;

    for (int i = tid; i < 1024*6; i += CL_THREADS) {
        int n = i / 6, q = i - n*6;
        size_t gi = base + (size_t)n*HHDIM + q*4;
        *(float4*)(fh + n*24 + q*4) = *(const float4*)(feat + gi);
        *(float4*)(vh + n*24 + q*4) = *(const float4*)(val + gi);
    }
    __syncthreads();

    for (int i = tid; i < 16*24; i += CL_THREADS) {
        int m = i / 24, c = i - m*24;
        int pr = m >> 2, pc = m & 3;
        float sf = 0.f, sv = 0.f;
        #pragma unroll
        for (int r = 0; r < 8; ++r) {
            int rowbase = ((pr*8 + r)*32 + pc*8)*24 + c;
            #pragma unroll
            for (int q = 0; q < 8; ++q) { sf += fh[rowbase + q*24]; sv += vh[rowbase + q*24]; }
        }
        cn[i] = sf * (1.0f/64.0f);
        vcen[i] = sv * (1.0f/64.0f);
        num[i] = 0.0f;
    }
    if (tid < 16) cnt[tid] = 0.0f;
    __syncthreads();

    if (tid < 16) {
        float s = 0.f;
        #pragma unroll
        for (int c = 0; c < 24; ++c) { float t = cn[tid*24 + c]; s += t*t; }
        float inv = 1.0f / fmaxf(sqrtf(s), 1e-12f);
        #pragma unroll
        for (int c = 0; c < 24; ++c) cn[tid*24 + c] *= inv;
    }
    __syncthreads();

    for (int n = tid; n < 1024; n += CL_THREADS) {
        float f[24]; float s2 = 0.f;
        #pragma unroll
        for (int c = 0; c < 24; ++c) { f[c] = fh[n*24 + c]; s2 += f[c]*f[c]; }
        float inv = 1.0f / fmaxf(sqrtf(s2), 1e-12f);
        float best = -1e30f; int bmx = 0;
        #pragma unroll
        for (int m = 0; m < 16; ++m) {
            float d = 0.f;
            #pragma unroll
            for (int c = 0; c < 24; ++c) d += cn[m*24 + c] * f[c];
            float s = beta + alpha * d * inv;
            s = (s >= 0.f) ? s : 0.2f*s;
            if (s > best) { best = s; bmx = m; }
        }
        sval[n] = best; sidx[n] = bmx;
        atomicAdd(&cnt[bmx], 1.0f);
        #pragma unroll
        for (int c = 0; c < 24; ++c) atomicAdd(&num[bmx*24 + c], best * vh[n*24 + c]);
    }
    __syncthreads();

    for (int i = tid; i < 16*24; i += CL_THREADS) {
        int m = i / 24;
        num[i] = (num[i] + vcen[i]) / (cnt[m] + 1.0f);
    }
    __syncthreads();

    for (int i = tid; i < 1024*24; i += CL_THREADS) {
        int n = i / 24, c = i - n*24;
        float v = sval[n] * num[sidx[n]*24 + c];
        out_hi[base + (size_t)n*HHDIM + c] = __float2half_rn(v);
    }
}

// ---------------- launch ----------------
extern "C" void kernel_launch(void* const* d_in, const int* in_sizes, int n_in,
                              void* d_out, int out_size) {
    const float* x      = (const float*)d_in[0];
    const float* ln1_g  = (const float*)d_in[1];
    const float* ln1_b  = (const float*)d_in[2];
    const float* f_w    = (const float*)d_in[3];
    const float* f_b    = (const float*)d_in[4];
    const float* v_w    = (const float*)d_in[5];
    const float* v_b    = (const float*)d_in[6];
    const float* alpha  = (const float*)d_in[7];
    const float* beta   = (const float*)d_in[8];
    const float* proj_w = (const float*)d_in[9];
    const float* proj_b = (const float*)d_in[10];
    const float* ln2_g  = (const float*)d_in[11];
    const float* ln2_b  = (const float*)d_in[12];
    const float* fc1_w  = (const float*)d_in[13];
    const float* fc1_b  = (const float*)d_in[14];
    const float* fc2_w  = (const float*)d_in[15];
    const float* fc2_b  = (const float*)d_in[16];
    float* out = (float*)d_out;

    fp16 *xn_hi, *xn_lo, *at_hi, *hid_hi;
    fp16 *fvw_hi, *fvw_lo, *pw_hi, *w1_hi, *w2_hi;
    float *feat, *val, *x1;
    cudaGetSymbolAddress((void**)&xn_hi, g_xn_hi);   cudaGetSymbolAddress((void**)&xn_lo, g_xn_lo);
    cudaGetSymbolAddress((void**)&feat,  g_feat);    cudaGetSymbolAddress((void**)&val,   g_val);
    cudaGetSymbolAddress((void**)&at_hi, g_at_hi);
    cudaGetSymbolAddress((void**)&x1,    g_x1);
    cudaGetSymbolAddress((void**)&hid_hi,g_hid_hi);
    cudaGetSymbolAddress((void**)&fvw_hi,g_fvw_hi);  cudaGetSymbolAddress((void**)&fvw_lo,g_fvw_lo);
    cudaGetSymbolAddress((void**)&pw_hi, g_pw_hi);
    cudaGetSymbolAddress((void**)&w1_hi, g_w1_hi);
    cudaGetSymbolAddress((void**)&w2_hi, g_w2_hi);

    const int SMS_FV = 3 * (2*128*80 + 2*64*80);   // 92160  (3-term, BN=64)
    const int SMS_1  = 3 * (128*80 + 128*80);      // 61440  (1-term, BN=128)
    cudaFuncSetAttribute(gemm_mma<64,3,1,1>,  cudaFuncAttributeMaxDynamicSharedMemorySize, SMS_FV);
    cudaFuncSetAttribute(gemm_mma<128,1,0,0>, cudaFuncAttributeMaxDynamicSharedMemorySize, SMS_1);
    cudaFuncSetAttribute(gemm_mma<128,2,0,0>, cudaFuncAttributeMaxDynamicSharedMemorySize, SMS_1);
    cudaFuncSetAttribute(cluster_kernel,  cudaFuncAttributeMaxDynamicSharedMemorySize, CL_SMEM);

    // 0. weight conversion (f+v concatenated hi/lo; proj/fc1/fc2 hi-only)
    cvt_kernel   <<<(HHDIM*DIM+255)/256, 256>>>(f_w, fvw_hi, fvw_lo, HHDIM*DIM);
    cvt_kernel   <<<(HHDIM*DIM+255)/256, 256>>>(v_w, fvw_hi + HHDIM*DIM,
                                                fvw_lo + HHDIM*DIM, HHDIM*DIM);
    cvt_hi_kernel<<<(DIM*HHDIM+255)/256, 256>>>(proj_w, pw_hi, DIM*HHDIM);
    cvt_hi_kernel<<<(HID*DIM+255)/256,   256>>>(fc1_w,  w1_hi, HID*DIM);
    cvt_hi_kernel<<<(DIM*HID+255)/256,   256>>>(fc2_w,  w2_hi, DIM*HID);

    // 1. LN1 -> xn hi/lo (fp16)
    ln_kernel<1><<<NROWS, 128>>>(x, ln1_g, ln1_b, xn_hi, xn_lo);

    // 2. fused f+v projections (3-term fp16, protects argmax): split epilogue
    gemm_mma<64,3,1,1><<<dim3(6, NROWS/128), 128, SMS_FV>>>(
        xn_hi, xn_lo, fvw_hi, fvw_lo, f_b, v_b, nullptr,
        feat, val, nullptr, HHDIM, DIM);

    // 3. clustering -> at_hi (fp16)
    cluster_kernel<<<BATCH*HEADS, CL_THREADS, CL_SMEM>>>(feat, val, alpha, beta, at_hi);

    // 4. proj + residual -> x1 (1-term fp16): [65536,192] @ [512,192]^T
    gemm_mma<128,1,0,0><<<dim3(4, NROWS/128), 128, SMS_1>>>(
        at_hi, nullptr, pw_hi, nullptr, proj_b, nullptr, x,
        x1, nullptr, nullptr, DIM, HHDIM);

    // 5. LN2 -> xn hi only
    ln_kernel<0><<<NROWS, 128>>>(x1, ln2_g, ln2_b, xn_hi, nullptr);

    // 6. fc1 + GELU -> hid (1-term fp16): [65536,512] @ [2048,512]^T
    gemm_mma<128,2,0,0><<<dim3(16, NROWS/128), 128, SMS_1>>>(
        xn_hi, nullptr, w1_hi, nullptr, fc1_b, nullptr, nullptr,
        nullptr, nullptr, hid_hi, HID, DIM);

    // 7. fc2 + residual -> out (1-term fp16): [65536,2048] @ [512,2048]^T
    gemm_mma<128,1,0,0><<<dim3(4, NROWS/128), 128, SMS_1>>>(
        hid_hi, nullptr, w2_hi, nullptr, fc2_b, nullptr, x1,
        out, nullptr, nullptr, DIM, HID);
}

// round 14
// speedup vs baseline: 1.3996x; 1.3996x over previous
#include <cuda_runtime.h>
#include <cuda_fp16.h>
#include <math.h>
#include <stdint.h>

#define BATCH   64
#define NTOK    1024
#define DIM     512
#define HEADS   8
#define HD      24
#define HHDIM   192
#define HID     2048
#define NROWS   (BATCH*NTOK)   // 65536

typedef __half fp16;

// ---------------- scratch (device globals) ----------------
__device__ fp16  g_xn_hi [(size_t)NROWS * DIM];
__device__ fp16  g_xn_lo [(size_t)NROWS * DIM];     // only used by f/v (LN1)
__device__ float g_feat  [(size_t)NROWS * HHDIM];
__device__ float g_val   [(size_t)NROWS * HHDIM];
__device__ fp16  g_at_hi [(size_t)NROWS * HHDIM];
__device__ float g_x1    [(size_t)NROWS * DIM];
__device__ fp16  g_hid_hi[(size_t)NROWS * HID];
// weights: f+v concatenated (384 rows) hi/lo; proj/fc1/fc2 hi-only
__device__ fp16  g_fvw_hi[2*HHDIM*DIM], g_fvw_lo[2*HHDIM*DIM];
__device__ fp16  g_pw_hi[DIM*HHDIM];
__device__ fp16  g_w1_hi[HID*DIM];
__device__ fp16  g_w2_hi[DIM*HID];

// ---------------- helpers ----------------
__device__ __forceinline__ uint32_t smem_u32(const void* p) {
    uint32_t a;
    asm("{ .reg .u64 t; cvta.to.shared.u64 t, %1; cvt.u32.u64 %0, t; }" : "=r"(a) : "l"(p));
    return a;
}
__device__ __forceinline__ void cp16(uint32_t saddr, const void* g) {
    asm volatile("cp.async.cg.shared.global [%0], [%1], 16;" :: "r"(saddr), "l"(g));
}
#define CP_COMMIT() asm volatile("cp.async.commit_group;" ::: "memory")
template<int N>
__device__ __forceinline__ void cp_wait() {
    asm volatile("cp.async.wait_group %0;" :: "n"(N) : "memory");
}
__device__ __forceinline__ void ldm_x4(uint32_t* r, uint32_t addr) {
    asm volatile("ldmatrix.sync.aligned.m8n8.x4.shared.b16 {%0,%1,%2,%3}, [%4];"
        : "=r"(r[0]), "=r"(r[1]), "=r"(r[2]), "=r"(r[3]) : "r"(addr));
}
__device__ __forceinline__ void mma_f16(float* c, const uint32_t* a, const uint32_t* b) {
    asm volatile(
        "mma.sync.aligned.m16n8k16.row.col.f32.f16.f16.f32 "
        "{%0,%1,%2,%3}, {%4,%5,%6,%7}, {%8,%9}, {%0,%1,%2,%3};"
        : "+f"(c[0]), "+f"(c[1]), "+f"(c[2]), "+f"(c[3])
        : "r"(a[0]), "r"(a[1]), "r"(a[2]), "r"(a[3]), "r"(b[0]), "r"(b[1]));
}

// ---------------- fp32 -> fp16 hi/lo conversions ----------------
__global__ void cvt_kernel(const float* __restrict__ s, fp16* __restrict__ hi,
                           fp16* __restrict__ lo, int n) {
    int i = blockIdx.x * blockDim.x + threadIdx.x;
    if (i < n) {
        float v = s[i];
        fp16 h = __float2half_rn(v);
        hi[i] = h;
        lo[i] = __float2half_rn(v - __half2float(h));
    }
}
__global__ void cvt_hi_kernel(const float* __restrict__ s, fp16* __restrict__ hi, int n) {
    int i = blockIdx.x * blockDim.x + threadIdx.x;
    if (i < n) hi[i] = __float2half_rn(s[i]);
}

// ---------------- LayerNorm -> fp16 hi (+ optional lo) ----------------
template<int WRITE_LO>
__global__ void ln_kernel(const float* __restrict__ x, const float* __restrict__ g,
                          const float* __restrict__ b, fp16* __restrict__ yh,
                          fp16* __restrict__ yl) {
    int row = blockIdx.x;
    const float4* xr = (const float4*)(x + (size_t)row * DIM);
    float4 v = xr[threadIdx.x];
    float s  = v.x + v.y + v.z + v.w;
    float sq = v.x*v.x + v.y*v.y + v.z*v.z + v.w*v.w;
    #pragma unroll
    for (int o = 16; o; o >>= 1) {
        s  += __shfl_down_sync(0xffffffffu, s,  o);
        sq += __shfl_down_sync(0xffffffffu, sq, o);
    }
    __shared__ float rs[4], rq[4];
    __shared__ float s_mean, s_rstd;
    int lane = threadIdx.x & 31, w = threadIdx.x >> 5;
    if (lane == 0) { rs[w] = s; rq[w] = sq; }
    __syncthreads();
    if (threadIdx.x == 0) {
        float S = rs[0]+rs[1]+rs[2]+rs[3];
        float Q = rq[0]+rq[1]+rq[2]+rq[3];
        float m = S * (1.0f/DIM);
        float var = Q * (1.0f/DIM) - m*m;
        s_mean = m; s_rstd = rsqrtf(var + 1e-5f);
    }
    __syncthreads();
    float m = s_mean, r = s_rstd;
    float4 gg = ((const float4*)g)[threadIdx.x];
    float4 bb = ((const float4*)b)[threadIdx.x];
    float o0 = (v.x-m)*r*gg.x + bb.x, o1 = (v.y-m)*r*gg.y + bb.y;
    float o2 = (v.z-m)*r*gg.z + bb.z, o3 = (v.w-m)*r*gg.w + bb.w;
    fp16 h0 = __float2half_rn(o0), h1 = __float2half_rn(o1);
    fp16 h2 = __float2half_rn(o2), h3 = __float2half_rn(o3);
    __half2* hp = (__half2*)(yh + (size_t)row*DIM);
    hp[2*threadIdx.x]   = __halves2half2(h0, h1);
    hp[2*threadIdx.x+1] = __halves2half2(h2, h3);
    if (WRITE_LO) {
        __half2* lp = (__half2*)(yl + (size_t)row*DIM);
        lp[2*threadIdx.x]   = __halves2half2(__float2half_rn(o0-__half2float(h0)),
                                             __float2half_rn(o1-__half2float(h1)));
        lp[2*threadIdx.x+1] = __halves2half2(__float2half_rn(o2-__half2float(h2)),
                                             __float2half_rn(o3-__half2float(h3)));
    }
}

// ---------------- HMMA GEMM: C = A @ B^T, fp16 (optionally hi/lo emulated) ----
// 128 threads, 4 warps in 2x2: warp tile 64 x (BN/2).
// KCH = 32-k sub-chunks per pipeline stage (1 or 2); NST = stages in ring.
// ALO: include Al*Bh term.  BLO: include Ah*Bl term.
// EPI 0: C=acc+bias (fp32)        EPI 1: C=acc+bias+Res (fp32)
// EPI 2: gelu(acc+bias) -> fp16   EPI 3: split output (cols<192 -> Cf/bias, else Cf2/bias2)
#define ROWB 80   // 64B data + 16B pad: conflict-free ldmatrix

template<int BN, int EPI, int ALO, int BLO, int KCH, int NST>
__global__ __launch_bounds__(128, 2)
void gemm_mma(const fp16* __restrict__ Ahi, const fp16* __restrict__ Alo,
              const fp16* __restrict__ Bhi, const fp16* __restrict__ Blo,
              const float* __restrict__ bias, const float* __restrict__ bias2,
              const float* __restrict__ Res,
              float* __restrict__ Cf, float* __restrict__ Cf2, fp16* __restrict__ Chi,
              int N, int K) {
    constexpr int NT = BN / 16;              // n8-tiles per warp (warp covers BN/2)
    constexpr int A_BYTES = 128 * ROWB;
    constexpr int B_BYTES = BN * ROWB;
    constexpr int SSUB = (1+ALO)*A_BYTES + (1+BLO)*B_BYTES;   // one 32-k sub-chunk
    constexpr int STAGE = KCH * SSUB;

    extern __shared__ char smem[];
    const uint32_t sbase = smem_u32(smem);
    const int tid  = threadIdx.x;
    const int wid  = tid >> 5;
    const int lane = tid & 31;
    const int warp_m = wid & 1;              // 2 m-groups of 64 rows
    const int warp_n = wid >> 1;             // 2 n-groups of BN/2 cols
    const int bm = blockIdx.y * 128;
    const int bn = blockIdx.x * BN;

    // ldmatrix lane geometry
    const int lr = lane & 7;
    const int g8 = lane >> 3;
    const int a_row0 = warp_m*64 + (g8 & 1)*8 + lr;       // + sub*16, sub=0..3
    const int a_ch   = (g8 >> 1);                          // +cb
    const int b_row0 = warp_n*(NT*8) + (g8 >> 1)*8 + lr;   // + t2*16
    const int b_ch   = (g8 & 1);                           // +cb

    float acc[4][NT][4];
    #pragma unroll
    for (int s = 0; s < 4; ++s)
        #pragma unroll
        for (int t = 0; t < NT; ++t)
            #pragma unroll
            for (int j = 0; j < 4; ++j) acc[s][t][j] = 0.0f;

    // load one stage = KCH consecutive 32-k chunks
    auto load_stage = [&](int st, int k0) {
        #pragma unroll
        for (int sc = 0; sc < KCH; ++sc) {
            uint32_t sA_hi = sbase + st*STAGE + sc*SSUB;
            uint32_t sA_lo = sA_hi + A_BYTES;
            uint32_t sB_hi = sA_hi + (1+ALO)*A_BYTES;
            uint32_t sB_lo = sB_hi + B_BYTES;
            int kk = k0 + sc*32;
            #pragma unroll
            for (int it = 0; it < 4; ++it) {            // A: 128 rows x 4 chunks
                int idx = tid + it*128;
                int r = idx >> 2, c = idx & 3;
                size_t go = (size_t)(bm + r)*K + kk + c*8;
                uint32_t so = (uint32_t)(r*ROWB + c*16);
                cp16(sA_hi + so, Ahi + go);
                if (ALO) cp16(sA_lo + so, Alo + go);
            }
            #pragma unroll
            for (int it = 0; it < BN/32; ++it) {        // B: BN rows x 4 chunks
                int idx = tid + it*128;
                int r = idx >> 2, c = idx & 3;
                size_t go = (size_t)(bn + r)*K + kk + c*8;
                uint32_t so = (uint32_t)(r*ROWB + c*16);
                cp16(sB_hi + so, Bhi + go);
                if (BLO) cp16(sB_lo + so, Blo + go);
            }
        }
    };

    const int niter = K / (32*KCH);
    load_stage(0, 0);        CP_COMMIT();
    load_stage(1 % NST, 32*KCH); CP_COMMIT();   // niter >= 2 always here

    for (int c = 0; c < niter; ++c) {
        cp_wait<1>();
        __syncthreads();
        int st = c % NST;
        #pragma unroll
        for (int sc = 0; sc < KCH; ++sc) {
            uint32_t sA_hi = sbase + st*STAGE + sc*SSUB;
            uint32_t sA_lo = sA_hi + A_BYTES;
            uint32_t sB_hi = sA_hi + (1+ALO)*A_BYTES;
            uint32_t sB_lo = sB_hi + B_BYTES;

            uint32_t ah[4][4], al[4][4], bb[NT][2];
            #pragma unroll
            for (int k16 = 0; k16 < 2; ++k16) {
                int cb = k16*2;
                #pragma unroll
                for (int sub = 0; sub < 4; ++sub) {
                    uint32_t ao = (uint32_t)((a_row0 + sub*16)*ROWB + (cb + a_ch)*16);
                    ldm_x4(ah[sub], sA_hi + ao);
                    if (ALO) ldm_x4(al[sub], sA_lo + ao);
                }
                #pragma unroll
                for (int t2 = 0; t2 < NT/2; ++t2) {
                    uint32_t bo = (uint32_t)((b_row0 + t2*16)*ROWB + (cb + b_ch)*16);
                    ldm_x4(&bb[2*t2][0], sB_hi + bo);
                }
                #pragma unroll
                for (int sub = 0; sub < 4; ++sub)
                    #pragma unroll
                    for (int t = 0; t < NT; ++t) {
                        mma_f16(acc[sub][t], ah[sub], bb[t]);            // hi*hi
                        if (ALO) mma_f16(acc[sub][t], al[sub], bb[t]);   // lo*hi
                    }
                if (BLO) {
                    #pragma unroll
                    for (int t2 = 0; t2 < NT/2; ++t2) {
                        uint32_t bo = (uint32_t)((b_row0 + t2*16)*ROWB + (cb + b_ch)*16);
                        ldm_x4(&bb[2*t2][0], sB_lo + bo);
                    }
                    #pragma unroll
                    for (int sub = 0; sub < 4; ++sub)
                        #pragma unroll
                        for (int t = 0; t < NT; ++t)
                            mma_f16(acc[sub][t], ah[sub], bb[t]);        // hi*lo
                }
            }
        }
        __syncthreads();
        if (c + 2 < niter) load_stage((c + 2) % NST, (c + 2)*32*KCH);
        CP_COMMIT();
    }

    // ---------------- epilogue ----------------
    const int mbase = bm + warp_m*64;
    const int nb0   = bn + warp_n*(NT*8);
    #pragma unroll
    for (int sub = 0; sub < 4; ++sub) {
        int r0 = mbase + sub*16 + (lane >> 2);
        #pragma unroll
        for (int t = 0; t < NT; ++t) {
            int c0 = nb0 + t*8 + (lane & 3)*2;
            float b0, b1;
            float* dst = Cf;
            int cc = c0;
            if (EPI == 3) {
                if (c0 >= HHDIM) { dst = Cf2; cc = c0 - HHDIM; b0 = bias2[cc]; b1 = bias2[cc+1]; }
                else             { b0 = bias[c0]; b1 = bias[c0+1]; }
            } else {
                b0 = bias[c0]; b1 = bias[c0+1];
            }
            float v00 = acc[sub][t][0] + b0, v01 = acc[sub][t][1] + b1;
            float v10 = acc[sub][t][2] + b0, v11 = acc[sub][t][3] + b1;
            size_t gi0 = (size_t)r0*N + cc;
            size_t gi1 = (size_t)(r0+8)*N + cc;
            if (EPI == 0 || EPI == 3) {
                *(float2*)(dst + gi0) = make_float2(v00, v01);
                *(float2*)(dst + gi1) = make_float2(v10, v11);
            } else if (EPI == 1) {
                float2 r0v = *(const float2*)(Res + gi0);
                float2 r1v = *(const float2*)(Res + gi1);
                *(float2*)(Cf + gi0) = make_float2(v00 + r0v.x, v01 + r0v.y);
                *(float2*)(Cf + gi1) = make_float2(v10 + r1v.x, v11 + r1v.y);
            } else {
                float g00 = 0.5f*v00*(1.0f + erff(v00*0.7071067811865475f));
                float g01 = 0.5f*v01*(1.0f + erff(v01*0.7071067811865475f));
                float g10 = 0.5f*v10*(1.0f + erff(v10*0.7071067811865475f));
                float g11 = 0.5f*v11*(1.0f + erff(v11*0.7071067811865475f));
                *(__half2*)(Chi + gi0) = __halves2half2(
                    __float2half_rn(g00), __float2half_rn(g01));
                *(__half2*)(Chi + gi1) = __halves2half2(
                    __float2half_rn(g10), __float2half_rn(g11));
            }
        }
    }
}

// ---------------- Cluster3D core: one block per (batch, head) ----------------
#define CL_SMEM ((1024*24*2 + 16*24*3 + 16 + 1024) * 4 + 1024 * 4)
#define CL_THREADS 512

__global__ __launch_bounds__(CL_THREADS, 1)
void cluster_kernel(const float* __restrict__ feat, const float* __restrict__ val,
                    const float* __restrict__ alpha_p, const float* __restrict__ beta_p,
                    fp16* __restrict__ out_hi) {
    extern __shared__ float sm[];
    float* fh   = sm;
    float* vh   = fh + 1024*24;
    float* cn   = vh + 1024*24;
    float* vcen = cn + 16*24;
    float* num  = vcen + 16*24;
    float* cnt  = num + 16*24;
    float* sval = cnt + 16;
    int*   sidx = (int*)(sval + 1024);

    const int bh = blockIdx.x;
    const int b  = bh >> 3;
    const int h  = bh & 7;
    const int tid = threadIdx.x;
    const float alpha = *alpha_p, beta = *beta_p;
    const size_t base = (size_t)b * NTOK * HHDIM + (size_t)h * HD;

    for (int i = tid; i < 1024*6; i += CL_THREADS) {
        int n = i / 6, q = i - n*6;
        size_t gi = base + (size_t)n*HHDIM + q*4;
        *(float4*)(fh + n*24 + q*4) = *(const float4*)(feat + gi);
        *(float4*)(vh + n*24 + q*4) = *(const float4*)(val + gi);
    }
    __syncthreads();

    for (int i = tid; i < 16*24; i += CL_THREADS) {
        int m = i / 24, c = i - m*24;
        int pr = m >> 2, pc = m & 3;
        float sf = 0.f, sv = 0.f;
        #pragma unroll
        for (int r = 0; r < 8; ++r) {
            int rowbase = ((pr*8 + r)*32 + pc*8)*24 + c;
            #pragma unroll
            for (int q = 0; q < 8; ++q) { sf += fh[rowbase + q*24]; sv += vh[rowbase + q*24]; }
        }
        cn[i] = sf * (1.0f/64.0f);
        vcen[i] = sv * (1.0f/64.0f);
        num[i] = 0.0f;
    }
    if (tid < 16) cnt[tid] = 0.0f;
    __syncthreads();

    if (tid < 16) {
        float s = 0.f;
        #pragma unroll
        for (int c = 0; c < 24; ++c) { float t = cn[tid*24 + c]; s += t*t; }
        float inv = 1.0f / fmaxf(sqrtf(s), 1e-12f);
        #pragma unroll
        for (int c = 0; c < 24; ++c) cn[tid*24 + c] *= inv;
    }
    __syncthreads();

    for (int n = tid; n < 1024; n += CL_THREADS) {
        float f[24]; float s2 = 0.f;
        #pragma unroll
        for (int c = 0; c < 24; ++c) { f[c] = fh[n*24 + c]; s2 += f[c]*f[c]; }
        float inv = 1.0f / fmaxf(sqrtf(s2), 1e-12f);
        float best = -1e30f; int bmx = 0;
        #pragma unroll
        for (int m = 0; m < 16; ++m) {
            float d = 0.f;
            #pragma unroll
            for (int c = 0; c < 24; ++c) d += cn[m*24 + c] * f[c];
            float s = beta + alpha * d * inv;
            s = (s >= 0.f) ? s : 0.2f*s;
            if (s > best) { best = s; bmx = m; }
        }
        sval[n] = best; sidx[n] = bmx;
        atomicAdd(&cnt[bmx], 1.0f);
        #pragma unroll
        for (int c = 0; c < 24; ++c) atomicAdd(&num[bmx*24 + c], best * vh[n*24 + c]);
    }
    __syncthreads();

    for (int i = tid; i < 16*24; i += CL_THREADS) {
        int m = i / 24;
        num[i] = (num[i] + vcen[i]) / (cnt[m] + 1.0f);
    }
    __syncthreads();

    for (int i = tid; i < 1024*24; i += CL_THREADS) {
        int n = i / 24, c = i - n*24;
        float v = sval[n] * num[sidx[n]*24 + c];
        out_hi[base + (size_t)n*HHDIM + c] = __float2half_rn(v);
    }
}

// ---------------- launch ----------------
extern "C" void kernel_launch(void* const* d_in, const int* in_sizes, int n_in,
                              void* d_out, int out_size) {
    const float* x      = (const float*)d_in[0];
    const float* ln1_g  = (const float*)d_in[1];
    const float* ln1_b  = (const float*)d_in[2];
    const float* f_w    = (const float*)d_in[3];
    const float* f_b    = (const float*)d_in[4];
    const float* v_w    = (const float*)d_in[5];
    const float* v_b    = (const float*)d_in[6];
    const float* alpha  = (const float*)d_in[7];
    const float* beta   = (const float*)d_in[8];
    const float* proj_w = (const float*)d_in[9];
    const float* proj_b = (const float*)d_in[10];
    const float* ln2_g  = (const float*)d_in[11];
    const float* ln2_b  = (const float*)d_in[12];
    const float* fc1_w  = (const float*)d_in[13];
    const float* fc1_b  = (const float*)d_in[14];
    const float* fc2_w  = (const float*)d_in[15];
    const float* fc2_b  = (const float*)d_in[16];
    float* out = (float*)d_out;

    fp16 *xn_hi, *xn_lo, *at_hi, *hid_hi;
    fp16 *fvw_hi, *fvw_lo, *pw_hi, *w1_hi, *w2_hi;
    float *feat, *val, *x1;
    cudaGetSymbolAddress((void**)&xn_hi, g_xn_hi);   cudaGetSymbolAddress((void**)&xn_lo, g_xn_lo);
    cudaGetSymbolAddress((void**)&feat,  g_feat);    cudaGetSymbolAddress((void**)&val,   g_val);
    cudaGetSymbolAddress((void**)&at_hi, g_at_hi);
    cudaGetSymbolAddress((void**)&x1,    g_x1);
    cudaGetSymbolAddress((void**)&hid_hi,g_hid_hi);
    cudaGetSymbolAddress((void**)&fvw_hi,g_fvw_hi);  cudaGetSymbolAddress((void**)&fvw_lo,g_fvw_lo);
    cudaGetSymbolAddress((void**)&pw_hi, g_pw_hi);
    cudaGetSymbolAddress((void**)&w1_hi, g_w1_hi);
    cudaGetSymbolAddress((void**)&w2_hi, g_w2_hi);

    // f/v 3-term: KCH=1, NST=3, stage 30720 -> 92160
    // 1-term:     KCH=2, NST=2, stage 40960 -> 81920
    const int SMS_FV = 3 * (2*128*80 + 2*64*80);        // 92160
    const int SMS_1  = 2 * 2 * (128*80 + 128*80);       // 81920
    cudaFuncSetAttribute(gemm_mma<64,3,1,1,1,3>,  cudaFuncAttributeMaxDynamicSharedMemorySize, SMS_FV);
    cudaFuncSetAttribute(gemm_mma<128,1,0,0,2,2>, cudaFuncAttributeMaxDynamicSharedMemorySize, SMS_1);
    cudaFuncSetAttribute(gemm_mma<128,2,0,0,2,2>, cudaFuncAttributeMaxDynamicSharedMemorySize, SMS_1);
    cudaFuncSetAttribute(cluster_kernel,  cudaFuncAttributeMaxDynamicSharedMemorySize, CL_SMEM);

    // 0. weight conversion (f+v concatenated hi/lo; proj/fc1/fc2 hi-only)
    cvt_kernel   <<<(HHDIM*DIM+255)/256, 256>>>(f_w, fvw_hi, fvw_lo, HHDIM*DIM);
    cvt_kernel   <<<(HHDIM*DIM+255)/256, 256>>>(v_w, fvw_hi + HHDIM*DIM,
                                                fvw_lo + HHDIM*DIM, HHDIM*DIM);
    cvt_hi_kernel<<<(DIM*HHDIM+255)/256, 256>>>(proj_w, pw_hi, DIM*HHDIM);
    cvt_hi_kernel<<<(HID*DIM+255)/256,   256>>>(fc1_w,  w1_hi, HID*DIM);
    cvt_hi_kernel<<<(DIM*HID+255)/256,   256>>>(fc2_w,  w2_hi, DIM*HID);

    // 1. LN1 -> xn hi/lo (fp16)
    ln_kernel<1><<<NROWS, 128>>>(x, ln1_g, ln1_b, xn_hi, xn_lo);

    // 2. fused f+v projections (3-term fp16, protects argmax): split epilogue
    gemm_mma<64,3,1,1,1,3><<<dim3(6, NROWS/128), 128, SMS_FV>>>(
        xn_hi, xn_lo, fvw_hi, fvw_lo, f_b, v_b, nullptr,
        feat, val, nullptr, HHDIM, DIM);

    // 3. clustering -> at_hi (fp16)
    cluster_kernel<<<BATCH*HEADS, CL_THREADS, CL_SMEM>>>(feat, val, alpha, beta, at_hi);

    // 4. proj + residual -> x1 (1-term fp16, BK=64): [65536,192] @ [512,192]^T
    gemm_mma<128,1,0,0,2,2><<<dim3(4, NROWS/128), 128, SMS_1>>>(
        at_hi, nullptr, pw_hi, nullptr, proj_b, nullptr, x,
        x1, nullptr, nullptr, DIM, HHDIM);

    // 5. LN2 -> xn hi only
    ln_kernel<0><<<NROWS, 128>>>(x1, ln2_g, ln2_b, xn_hi, nullptr);

    // 6. fc1 + GELU -> hid (1-term fp16, BK=64): [65536,512] @ [2048,512]^T
    gemm_mma<128,2,0,0,2,2><<<dim3(16, NROWS/128), 128, SMS_1>>>(
        xn_hi, nullptr, w1_hi, nullptr, fc1_b, nullptr, nullptr,
        nullptr, nullptr, hid_hi, HID, DIM);

    // 7. fc2 + residual -> out (1-term fp16, BK=64): [65536,2048] @ [512,2048]^T
    gemm_mma<128,1,0,0,2,2><<<dim3(4, NROWS/128), 128, SMS_1>>>(
        hid_hi, nullptr, w2_hi, nullptr, fc2_b, nullptr, x1,
        out, nullptr, nullptr, DIM, HID);
}